// round 15
// baseline (speedup 1.0000x reference)
#include <cuda_runtime.h>
#include <cuda_bf16.h>
#include <cuda_fp16.h>
#include <math.h>
#include <stdint.h>

#define NLAYER 50
#define BATCH 8
#define CIN 256
#define LFULL 16384
#define NRES 32
#define NSKIP 512
#define FINALW 11269
#define TT 128
#define TTP 132
#define TT2 256
#define TTP2 260

// ---------------- scratch (static __device__, no allocs) ----------------
__device__ float g_buf0[(size_t)BATCH * NRES * LFULL];
__device__ float g_buf1[(size_t)BATCH * NRES * LFULL];
// activations: single fp16 planes, transposed [b][t][k]
__device__ __align__(16) __half g_gateT[(size_t)BATCH * FINALW * 1600];  // 288 MB
__device__ __align__(16) __half g_h1T[(size_t)BATCH * FINALW * 512];
__device__ __align__(16) __half g_h2T[(size_t)BATCH * FINALW * 512];
// GEMM weights: fp16 hi/lo planes [m][k]
__device__ __align__(16) __half g_A0hi[512 * 1600];
__device__ __align__(16) __half g_A0lo[512 * 1600];
__device__ __align__(16) __half g_A1hi[512 * 512];
__device__ __align__(16) __half g_A1lo[512 * 512];
__device__ __align__(16) __half g_A2hi[256 * 512];
__device__ __align__(16) __half g_A2lo[256 * 512];
// per-layer gate-conv weights [l][o(64)][k(64)] (o<32: sig, o>=32: tanh; k = c + 32*tap)
__device__ __align__(16) __nv_bfloat16 g_Wgh[NLAYER * 64 * 64];
__device__ __align__(16) __nv_bfloat16 g_Wgl[NLAYER * 64 * 64];
// per-layer res-conv weights [l][o(32)][c(32)]
__device__ __align__(16) __nv_bfloat16 g_Wrh[NLAYER * 32 * 32];
__device__ __align__(16) __nv_bfloat16 g_Wrl[NLAYER * 32 * 32];
__device__ float g_sumb[NSKIP];

// ---------------- helpers ----------------
__device__ __forceinline__ uint32_t smem_to_u32(const void* p) {
    uint32_t a;
    asm("{ .reg .u64 t; cvta.to.shared.u64 t, %1; cvt.u32.u64 %0, t; }" : "=r"(a) : "l"(p));
    return a;
}
__device__ __forceinline__ void ldsm4(uint32_t& r0, uint32_t& r1, uint32_t& r2, uint32_t& r3,
                                      uint32_t addr) {
    asm volatile("ldmatrix.sync.aligned.m8n8.x4.shared.b16 {%0,%1,%2,%3}, [%4];"
                 : "=r"(r0), "=r"(r1), "=r"(r2), "=r"(r3) : "r"(addr));
}
__device__ __forceinline__ void mma16816(float* c, const uint32_t* a, uint32_t b0, uint32_t b1) {
    asm volatile(
        "mma.sync.aligned.m16n8k16.row.col.f32.bf16.bf16.f32 "
        "{%0,%1,%2,%3}, {%4,%5,%6,%7}, {%8,%9}, {%0,%1,%2,%3};"
        : "+f"(c[0]), "+f"(c[1]), "+f"(c[2]), "+f"(c[3])
        : "r"(a[0]), "r"(a[1]), "r"(a[2]), "r"(a[3]), "r"(b0), "r"(b1));
}
__device__ __forceinline__ void mma16816h(float* c, const uint32_t* a, uint32_t b0, uint32_t b1) {
    asm volatile(
        "mma.sync.aligned.m16n8k16.row.col.f32.f16.f16.f32 "
        "{%0,%1,%2,%3}, {%4,%5,%6,%7}, {%8,%9}, {%0,%1,%2,%3};"
        : "+f"(c[0]), "+f"(c[1]), "+f"(c[2]), "+f"(c[3])
        : "r"(a[0]), "r"(a[1]), "r"(a[2]), "r"(a[3]), "r"(b0), "r"(b1));
}
__device__ __forceinline__ uint32_t cvt2(float a, float b) {
    uint32_t r;
    asm("cvt.rn.bf16x2.f32 %0, %1, %2;" : "=r"(r) : "f"(b), "f"(a));
    return r;
}
__device__ __forceinline__ uint32_t cvt2lo(float a, float b, uint32_t hi) {
    float ra = a - __uint_as_float(hi << 16);
    float rb = b - __uint_as_float(hi & 0xFFFF0000u);
    return cvt2(ra, rb);
}
// cp.async
__device__ __forceinline__ void cpa16(uint32_t dst, const void* src) {
    asm volatile("cp.async.cg.shared.global [%0], [%1], 16;" :: "r"(dst), "l"(src));
}
__device__ __forceinline__ void cpa16z(uint32_t dst, const void* src, bool pred) {
    int sz = pred ? 16 : 0;
    asm volatile("cp.async.cg.shared.global [%0], [%1], 16, %2;" :: "r"(dst), "l"(src),
                 "r"(sz));
}
#define CP_COMMIT() asm volatile("cp.async.commit_group;" ::: "memory")
#define CP_WAIT(N) asm volatile("cp.async.wait_group %0;" :: "n"(N) : "memory")
__device__ __forceinline__ float elu_f(float v) {
    return v > 0.f ? v : (__expf(v) - 1.f);
}

// ---------------- weight packing + bias pre-sum ----------------
__global__ void k_pack(const float* __restrict__ wsk, const float* __restrict__ bsk,
                       const float* __restrict__ w1, const float* __restrict__ w2,
                       const float* __restrict__ wsig, const float* __restrict__ wtanh,
                       const float* __restrict__ wres) {
    int idx = blockIdx.x * blockDim.x + threadIdx.x;
    const int T0 = 512 * 1600;
    if (idx < T0) {
        int m = idx / 1600, k = idx - m * 1600;
        float v = wsk[(size_t)(k >> 5) * (512 * 32) + m * 32 + (k & 31)];
        __half h = __float2half_rn(v);
        g_A0hi[idx] = h;
        g_A0lo[idx] = __float2half_rn(v - __half2float(h));
    }
    int i1 = idx - T0;
    if (i1 >= 0 && i1 < 512 * 512) {
        float v = w1[i1];
        __half h = __float2half_rn(v);
        g_A1hi[i1] = h;
        g_A1lo[i1] = __float2half_rn(v - __half2float(h));
    }
    int i2 = idx - T0 - 512 * 512;
    if (i2 >= 0 && i2 < 256 * 512) {
        float v = w2[i2];
        __half h = __float2half_rn(v);
        g_A2hi[i2] = h;
        g_A2lo[i2] = __float2half_rn(v - __half2float(h));
    }
    int i3 = idx - T0 - 512 * 512 - 256 * 512;
    if (i3 >= 0 && i3 < NLAYER * 64 * 64) {
        int l = i3 >> 12, rem = i3 & 4095;
        int o = rem >> 6, k = rem & 63;
        int c = k & 31, tap = k >> 5;
        float v = (o < 32) ? wsig[l * 2048 + o * 64 + c * 2 + tap]
                           : wtanh[l * 2048 + (o - 32) * 64 + c * 2 + tap];
        __nv_bfloat16 h = __float2bfloat16(v);
        g_Wgh[i3] = h;
        g_Wgl[i3] = __float2bfloat16(v - __bfloat162float(h));
    }
    int i4 = i3 - NLAYER * 64 * 64;
    if (i4 >= 0 && i4 < NLAYER * 32 * 32) {
        float v = wres[i4];
        __nv_bfloat16 h = __float2bfloat16(v);
        g_Wrh[i4] = h;
        g_Wrl[i4] = __float2bfloat16(v - __bfloat162float(h));
    }
    if (idx < 512) {
        float s = 0.f;
        for (int i = 0; i < NLAYER; i++) s += bsk[i * 512 + idx];
        g_sumb[idx] = s;
    }
}

// ---------------- input 1x1 conv: 256 -> 32 ----------------
__global__ __launch_bounds__(256) void k_input(const float* __restrict__ x,
                                               const float* __restrict__ w,
                                               const float* __restrict__ b) {
    __shared__ float sx[32][TT];
    __shared__ float sw[32][32];
    const int bb = blockIdx.y;
    const int t0 = blockIdx.x * TT;
    const int tid = threadIdx.x;
    const int o = tid & 31, tq = tid >> 5;
    const int tb = tq * 16;
    float acc[16];
    {
        float bo = b[o];
#pragma unroll
        for (int j = 0; j < 16; j++) acc[j] = bo;
    }
    for (int cc = 0; cc < CIN; cc += 32) {
        for (int idx = tid; idx < 32 * TT; idx += 256) {
            int c = idx >> 7, tt = idx & 127;
            sx[c][tt] = x[(size_t)(bb * CIN + cc + c) * LFULL + t0 + tt];
        }
        for (int idx = tid; idx < 1024; idx += 256) {
            int oo = idx & 31, c = idx >> 5;
            sw[c][oo] = w[oo * CIN + cc + c];
        }
        __syncthreads();
#pragma unroll 4
        for (int c = 0; c < 32; c++) {
            float wv = sw[c][o];
            const float2* ap = reinterpret_cast<const float2*>(&sx[c][tb]);
#pragma unroll
            for (int j2 = 0; j2 < 8; j2++) {
                float2 a = ap[j2];
                acc[2 * j2] += wv * a.x;
                acc[2 * j2 + 1] += wv * a.y;
            }
        }
        __syncthreads();
    }
#pragma unroll
    for (int j = 0; j < 16; j++) sx[o][(tb + j + o) & 127] = acc[j];
    __syncthreads();
    for (int idx = tid; idx < 32 * TT; idx += 256) {
        int c = idx >> 7, tt = idx & 127;
        g_buf0[(size_t)(bb * NRES + c) * LFULL + t0 + tt] = sx[c][(tt + c) & 127];
    }
}

// ---------------- one residual layer: all-mma, TT=256 (two 16-t groups/warp) --------
#define SA0_B 0
#define SA1_B 33280
#define WGH_B 66560
#define WGL_B 75776
#define WRH_B 84992
#define WRL_B 89600
#define SBIAS_B 94208
#define LSM_BYTES 94592
__global__ __launch_bounds__(256, 2) void k_layer(int flag, const float* __restrict__ bsig,
                                                  const float* __restrict__ btanh,
                                                  const float* __restrict__ bres, int d,
                                                  int Lin, int Ls, int Lo_s, int layer) {
    const int Lout = Lin - d;
    const float* in = flag ? g_buf1 : g_buf0;
    float* outp = flag ? g_buf0 : g_buf1;
    extern __shared__ char smc[];
    float* sA0 = reinterpret_cast<float*>(smc + SA0_B);  // [32][260]
    float* sA1 = reinterpret_cast<float*>(smc + SA1_B);  // [32][260]
    float* sBias = reinterpret_cast<float*>(smc + SBIAS_B);
    const uint32_t smem_u = smem_to_u32(smc);
    const int b = blockIdx.y;
    const int t0 = blockIdx.x * TT2;
    const int tid = threadIdx.x;

    {
        const __nv_bfloat16* Wh = g_Wgh + layer * 4096;
        const __nv_bfloat16* Wl = g_Wgl + layer * 4096;
        for (int i = tid; i < 512; i += 256) {
            int row = i >> 3, ch = i & 7;
            *reinterpret_cast<uint4*>(smc + WGH_B + row * 144 + ch * 16) =
                *reinterpret_cast<const uint4*>(Wh + row * 64 + ch * 8);
            *reinterpret_cast<uint4*>(smc + WGL_B + row * 144 + ch * 16) =
                *reinterpret_cast<const uint4*>(Wl + row * 64 + ch * 8);
        }
        const __nv_bfloat16* Rh = g_Wrh + layer * 1024;
        const __nv_bfloat16* Rl = g_Wrl + layer * 1024;
        if (tid < 128) {
            int row = tid >> 2, ch = tid & 3;
            *reinterpret_cast<uint4*>(smc + WRH_B + row * 144 + ch * 16) =
                *reinterpret_cast<const uint4*>(Rh + row * 32 + ch * 8);
            *reinterpret_cast<uint4*>(smc + WRL_B + row * 144 + ch * 16) =
                *reinterpret_cast<const uint4*>(Rl + row * 32 + ch * 8);
        }
    }
    if (tid < 32) {
        sBias[tid] = bsig[tid];
        sBias[32 + tid] = btanh[tid];
        sBias[64 + tid] = bres[tid];
    }
    const float* inb = in + (size_t)b * NRES * Ls;
    const bool fulltile = (t0 + TT2 <= Lout);
    if (fulltile) {
        if ((d & 3) == 0) {
            for (int idx = tid; idx < 2048; idx += 256) {
                int c = idx >> 6, q = idx & 63;
                int t = t0 + 4 * q;
                const float* r = inb + (size_t)c * Ls;
                *reinterpret_cast<float4*>(&sA0[c * TTP2 + 4 * q]) =
                    *reinterpret_cast<const float4*>(r + t);
                *reinterpret_cast<float4*>(&sA1[c * TTP2 + 4 * q]) =
                    *reinterpret_cast<const float4*>(r + t + d);
            }
        } else {
            for (int idx = tid; idx < 2048; idx += 256) {
                int c = idx >> 6, q = idx & 63;
                int t = t0 + 4 * q;
                const float* r = inb + (size_t)c * Ls;
                *reinterpret_cast<float4*>(&sA0[c * TTP2 + 4 * q]) =
                    *reinterpret_cast<const float4*>(r + t);
                float4 v1;
                v1.x = r[t + d + 0];
                v1.y = r[t + d + 1];
                v1.z = r[t + d + 2];
                v1.w = r[t + d + 3];
                *reinterpret_cast<float4*>(&sA1[c * TTP2 + 4 * q]) = v1;
            }
        }
    } else {
        for (int idx = tid; idx < 2048; idx += 256) {
            int c = idx >> 6, q = idx & 63;
            int t = t0 + 4 * q;
            const float* r = inb + (size_t)c * Ls;
            float4 v0, v1;
            v0.x = (t + 0 < Lin) ? r[t + 0] : 0.f;
            v0.y = (t + 1 < Lin) ? r[t + 1] : 0.f;
            v0.z = (t + 2 < Lin) ? r[t + 2] : 0.f;
            v0.w = (t + 3 < Lin) ? r[t + 3] : 0.f;
            v1.x = (t + 0 < Lout) ? r[t + d + 0] : 0.f;
            v1.y = (t + 1 < Lout) ? r[t + d + 1] : 0.f;
            v1.z = (t + 2 < Lout) ? r[t + d + 2] : 0.f;
            v1.w = (t + 3 < Lout) ? r[t + d + 3] : 0.f;
            *reinterpret_cast<float4*>(&sA0[c * TTP2 + 4 * q]) = v0;
            *reinterpret_cast<float4*>(&sA1[c * TTP2 + 4 * q]) = v1;
        }
    }
    __syncthreads();  // ---- the ONLY block sync

    const int w = tid >> 5, lane = tid & 31;
    const int g = lane >> 2, tc = lane & 3;
    const uint32_t bpair = (uint32_t)((((lane >> 4) & 1) * 8 + (lane & 7)) * 144 +
                                      ((lane >> 3) & 1) * 16);
    const int off = Lout - FINALW;
    float* outb = outp + (size_t)b * NRES * Lo_s;

#pragma unroll
    for (int g16 = 0; g16 < 2; g16++) {
        const int tl = (w << 5) + (g16 << 4) + g;
        float acc[8][4];
#pragma unroll
        for (int ni = 0; ni < 8; ni++)
#pragma unroll
            for (int e = 0; e < 4; e++) acc[ni][e] = 0.f;

#pragma unroll
        for (int s = 0; s < 4; s++) {
            const float* sp = (s < 2) ? sA0 : sA1;
            const int cb = ((s & 1) << 4) + (tc << 1);
            float x00 = sp[cb * TTP2 + tl], x01 = sp[(cb + 1) * TTP2 + tl];
            float x10 = sp[cb * TTP2 + tl + 8], x11 = sp[(cb + 1) * TTP2 + tl + 8];
            float x20 = sp[(cb + 8) * TTP2 + tl], x21 = sp[(cb + 9) * TTP2 + tl];
            float x30 = sp[(cb + 8) * TTP2 + tl + 8], x31 = sp[(cb + 9) * TTP2 + tl + 8];
            uint32_t ahi[4], alo[4];
            ahi[0] = cvt2(x00, x01); alo[0] = cvt2lo(x00, x01, ahi[0]);
            ahi[1] = cvt2(x10, x11); alo[1] = cvt2lo(x10, x11, ahi[1]);
            ahi[2] = cvt2(x20, x21); alo[2] = cvt2lo(x20, x21, ahi[2]);
            ahi[3] = cvt2(x30, x31); alo[3] = cvt2lo(x30, x31, ahi[3]);
#pragma unroll
            for (int ni2 = 0; ni2 < 4; ni2++) {
                uint32_t ro = smem_u + bpair + (uint32_t)(ni2 * 16 * 144 + s * 32);
                uint32_t e0, e1, o0, o1, f0, f1, p0, p1;
                ldsm4(e0, e1, o0, o1, ro + WGH_B);
                ldsm4(f0, f1, p0, p1, ro + WGL_B);
                mma16816(acc[2 * ni2], ahi, e0, e1);
                mma16816(acc[2 * ni2], alo, e0, e1);
                mma16816(acc[2 * ni2], ahi, f0, f1);
                mma16816(acc[2 * ni2 + 1], ahi, o0, o1);
                mma16816(acc[2 * ni2 + 1], alo, o0, o1);
                mma16816(acc[2 * ni2 + 1], ahi, p0, p1);
            }
        }

        float gate[4][4];
#pragma unroll
        for (int ni = 0; ni < 4; ni++) {
            int n0 = ni * 8 + 2 * tc;
            float bs0 = sBias[n0], bs1 = sBias[n0 + 1];
            float bt0 = sBias[32 + n0], bt1 = sBias[32 + n0 + 1];
#pragma unroll
            for (int h = 0; h < 2; h++) {
                float ds0 = acc[ni][2 * h] + bs0, dt0 = acc[ni + 4][2 * h] + bt0;
                float ds1 = acc[ni][2 * h + 1] + bs1, dt1 = acc[ni + 4][2 * h + 1] + bt1;
                float s0 = __fdividef(1.f, 1.f + __expf(-ds0));
                float s1 = __fdividef(1.f, 1.f + __expf(-ds1));
                float th0 = 1.f - __fdividef(2.f, __expf(2.f * dt0) + 1.f);
                float th1 = 1.f - __fdividef(2.f, __expf(2.f * dt1) + 1.f);
                gate[ni][2 * h] = s0 * th0;
                gate[ni][2 * h + 1] = s1 * th1;
            }
        }

        float racc[4][4];
#pragma unroll
        for (int ot = 0; ot < 4; ot++) {
            int n0 = ot * 8 + 2 * tc;
            racc[ot][0] = sBias[64 + n0];
            racc[ot][1] = sBias[64 + n0 + 1];
            racc[ot][2] = racc[ot][0];
            racc[ot][3] = racc[ot][1];
        }
#pragma unroll
        for (int kk = 0; kk < 2; kk++) {
            uint32_t ah[4], al[4];
            ah[0] = cvt2(gate[2 * kk][0], gate[2 * kk][1]);
            al[0] = cvt2lo(gate[2 * kk][0], gate[2 * kk][1], ah[0]);
            ah[1] = cvt2(gate[2 * kk][2], gate[2 * kk][3]);
            al[1] = cvt2lo(gate[2 * kk][2], gate[2 * kk][3], ah[1]);
            ah[2] = cvt2(gate[2 * kk + 1][0], gate[2 * kk + 1][1]);
            al[2] = cvt2lo(gate[2 * kk + 1][0], gate[2 * kk + 1][1], ah[2]);
            ah[3] = cvt2(gate[2 * kk + 1][2], gate[2 * kk + 1][3]);
            al[3] = cvt2lo(gate[2 * kk + 1][2], gate[2 * kk + 1][3], ah[3]);
#pragma unroll
            for (int ot2 = 0; ot2 < 2; ot2++) {
                uint32_t ro = smem_u + bpair + (uint32_t)(ot2 * 16 * 144 + kk * 32);
                uint32_t e0, e1, o0, o1, f0, f1, p0, p1;
                ldsm4(e0, e1, o0, o1, ro + WRH_B);
                ldsm4(f0, f1, p0, p1, ro + WRL_B);
                mma16816(racc[2 * ot2], ah, e0, e1);
                mma16816(racc[2 * ot2], al, e0, e1);
                mma16816(racc[2 * ot2], ah, f0, f1);
                mma16816(racc[2 * ot2 + 1], ah, o0, o1);
                mma16816(racc[2 * ot2 + 1], al, o0, o1);
                mma16816(racc[2 * ot2 + 1], ah, p0, p1);
            }
        }

        // stage gate (warp-private columns)
#pragma unroll
        for (int ni = 0; ni < 4; ni++) {
            int n0 = ni * 8 + 2 * tc;
#pragma unroll
            for (int h = 0; h < 2; h++) {
                int t = tl + 8 * h;
                sA0[n0 * TTP2 + t] = gate[ni][2 * h];
                sA0[(n0 + 1) * TTP2 + t] = gate[ni][2 * h + 1];
            }
        }

        // residual add + direct global store
#pragma unroll
        for (int ot = 0; ot < 4; ot++) {
            int cbase = ot * 8 + 2 * tc;
#pragma unroll
            for (int h = 0; h < 2; h++) {
                int t = t0 + tl + 8 * h;
                if (t < Lout) {
                    float a0 = sA1[cbase * TTP2 + tl + 8 * h];
                    float a1 = sA1[(cbase + 1) * TTP2 + tl + 8 * h];
                    outb[(size_t)cbase * Lo_s + t] = racc[ot][2 * h] + a0;
                    outb[(size_t)(cbase + 1) * Lo_s + t] = racc[ot][2 * h + 1] + a1;
                }
            }
        }
        __syncwarp();

        // gate -> single fp16 plane [b][t][layer*32 + c]
#pragma unroll
        for (int k = 0; k < 8; k++) {
            int idx = lane + 32 * k;
            int ttl = idx >> 4, cp = idx & 15;
            int tt = (w << 5) + (g16 << 4) + ttl;
            int t = t0 + tt;
            if (t < Lout && t >= off) {
                int c2 = 2 * cp;
                float v0 = sA0[c2 * TTP2 + tt];
                float v1 = sA0[(c2 + 1) * TTP2 + tt];
                size_t oo = ((size_t)b * FINALW + (t - off)) * 1600 + layer * 32 + c2;
                *reinterpret_cast<__half2*>(g_gateT + oo) = __floats2half2_rn(v0, v1);
            }
        }
    }
}

// ---- unified fp16 2-term GEMM: C = (Ah + Al) * B, CTA 128m x 128n, 4 warps ----
#define LROW2 80
#define A_LO_OFF0 10240
#define B_OFF0 20480
#define STAGE0 30720
#define GSM0_BYTES 67584
template <int MODE>
__global__ __launch_bounds__(128, 2) void k_wmma(const float* __restrict__ bias_in,
                                                 float* __restrict__ Cext) {
    constexpr int K = (MODE == 0) ? 1600 : 512;
    constexpr int NC = K / 32;
    const __half* Ahi = (MODE == 0) ? g_A0hi : (MODE == 1) ? g_A1hi : g_A2hi;
    const __half* Alo = (MODE == 0) ? g_A0lo : (MODE == 1) ? g_A1lo : g_A2lo;
    const __half* Bp = (MODE == 0) ? g_gateT : (MODE == 1) ? g_h1T : g_h2T;

    extern __shared__ char smem[];
    const uint32_t smem_u = smem_to_u32(smem);
    const int tid = threadIdx.x, wid = tid >> 5, lane = tid & 31;
    const int m0 = blockIdx.x * 128;
    const int t0 = blockIdx.y * 128;
    const int b = blockIdx.z;
    const int wm = (wid >> 1) * 64, wn = (wid & 1) * 64;

    const __half* Brp = Bp + (size_t)b * FINALW * K;

    float acc[4][8][4];
#pragma unroll
    for (int mi = 0; mi < 4; mi++)
#pragma unroll
        for (int ni = 0; ni < 8; ni++)
#pragma unroll
            for (int e = 0; e < 4; e++) acc[mi][ni][e] = 0.f;

    const uint32_t rA4 = (wm + (lane & 15)) * LROW2 + (lane >> 4) * 16;
    const uint32_t rB4 = B_OFF0 + (wn + ((lane >> 4) & 1) * 8 + (lane & 7)) * LROW2 +
                         ((lane >> 3) & 1) * 16;

    const int lrow = tid >> 2, lunit = tid & 3;

    auto load_chunk = [&](int ch, int buf) {
        const uint32_t st = smem_u + buf * STAGE0;
        const int k0 = ch * 32;
#pragma unroll
        for (int i = 0; i < 4; i++) {
            int r = lrow + 32 * i;
            uint32_t soff = (uint32_t)(r * LROW2 + lunit * 16);
            size_t aoff = (size_t)(m0 + r) * K + k0 + lunit * 8;
            cpa16(st + soff, Ahi + aoff);
            cpa16(st + A_LO_OFF0 + soff, Alo + aoff);
            int t = t0 + r;
            bool pr = t < FINALW;
            int tcl = pr ? t : (FINALW - 1);
            cpa16z(st + B_OFF0 + soff, Brp + (size_t)tcl * K + k0 + lunit * 8, pr);
        }
        CP_COMMIT();
    };

    load_chunk(0, 0);
    for (int ch = 0; ch < NC; ch++) {
        if (ch + 1 < NC) {
            load_chunk(ch + 1, (ch + 1) & 1);
            CP_WAIT(1);
        } else {
            CP_WAIT(0);
        }
        __syncthreads();
        const uint32_t base = smem_u + (ch & 1) * STAGE0;
        const uint32_t aAh = base + rA4, aAl = aAh + A_LO_OFF0;
        const uint32_t aB4 = base + rB4;
#pragma unroll
        for (int k16 = 0; k16 < 2; k16++) {
            uint32_t ah[4][4], al[4][4];
#pragma unroll
            for (int mi = 0; mi < 4; mi++) {
                ldsm4(ah[mi][0], ah[mi][1], ah[mi][2], ah[mi][3],
                      aAh + mi * (16 * LROW2) + k16 * 32);
                ldsm4(al[mi][0], al[mi][1], al[mi][2], al[mi][3],
                      aAl + mi * (16 * LROW2) + k16 * 32);
            }
#pragma unroll
            for (int ni2 = 0; ni2 < 4; ni2++) {
                uint32_t e0, e1, o0, o1;
                ldsm4(e0, e1, o0, o1, aB4 + ni2 * (16 * LROW2) + k16 * 32);
#pragma unroll
                for (int mi = 0; mi < 4; mi++) {
                    mma16816h(acc[mi][2 * ni2], ah[mi], e0, e1);
                    mma16816h(acc[mi][2 * ni2], al[mi], e0, e1);
                    mma16816h(acc[mi][2 * ni2 + 1], ah[mi], o0, o1);
                    mma16816h(acc[mi][2 * ni2 + 1], al[mi], o0, o1);
                }
            }
        }
        __syncthreads();
    }

    // ---- epilogue ----
    const int g = lane >> 2, tig = lane & 3;
    const float* bias = (MODE == 0) ? g_sumb : bias_in;
    float bv[4][2];
#pragma unroll
    for (int mi = 0; mi < 4; mi++)
#pragma unroll
        for (int h = 0; h < 2; h++) bv[mi][h] = bias[m0 + wm + mi * 16 + g + 8 * h];

    if (MODE == 2) {
#pragma unroll
        for (int mi = 0; mi < 4; mi++)
#pragma unroll
            for (int ni = 0; ni < 8; ni++)
#pragma unroll
                for (int h = 0; h < 2; h++)
#pragma unroll
                    for (int p = 0; p < 2; p++) {
                        int t = t0 + wn + ni * 8 + 2 * tig + p;
                        if (t < FINALW) {
                            int m = m0 + wm + mi * 16 + g + 8 * h;
                            Cext[((size_t)b * 256 + m) * FINALW + t] =
                                acc[mi][ni][h * 2 + p] + bv[mi][h];
                        }
                    }
        return;
    }

    __syncthreads();
    float* sT = reinterpret_cast<float*>(smem);  // [128 n][132]
#pragma unroll
    for (int mi = 0; mi < 4; mi++)
#pragma unroll
        for (int ni = 0; ni < 8; ni++)
#pragma unroll
            for (int h = 0; h < 2; h++)
#pragma unroll
                for (int p = 0; p < 2; p++) {
                    float v = elu_f(acc[mi][ni][h * 2 + p] + bv[mi][h]);
                    int n = wn + ni * 8 + 2 * tig + p;
                    int m = wm + mi * 16 + g + 8 * h;
                    sT[n * 132 + m] = v;
                }
    __syncthreads();
    __half* Op = (MODE == 0) ? g_h1T : g_h2T;
    for (int idx = tid; idx < 128 * 64; idx += 128) {
        int t = idx >> 6, mp = idx & 63;
        int tg = t0 + t;
        if (tg < FINALW) {
            float v0 = sT[t * 132 + 2 * mp];
            float v1 = sT[t * 132 + 2 * mp + 1];
            size_t o = ((size_t)b * FINALW + tg) * 512 + m0 + 2 * mp;
            *reinterpret_cast<__half2*>(Op + o) = __floats2half2_rn(v0, v1);
        }
    }
}

// ---------------- launch ----------------
extern "C" void kernel_launch(void* const* d_in, const int* in_sizes, int n_in,
                              void* d_out, int out_size) {
    (void)in_sizes; (void)n_in; (void)out_size;
    const float* x = (const float*)d_in[0];
    const float* w_in = (const float*)d_in[1];
    const float* b_in = (const float*)d_in[2];
    const float* w_sig = (const float*)d_in[3];
    const float* b_sig = (const float*)d_in[4];
    const float* w_tanh = (const float*)d_in[5];
    const float* b_tanh = (const float*)d_in[6];
    const float* w_skip = (const float*)d_in[7];
    const float* b_skip = (const float*)d_in[8];
    const float* w_res = (const float*)d_in[9];
    const float* b_res = (const float*)d_in[10];
    const float* w_post1 = (const float*)d_in[11];
    const float* b_post1 = (const float*)d_in[12];
    const float* w_post2 = (const float*)d_in[13];
    const float* b_post2 = (const float*)d_in[14];
    float* out = (float*)d_out;

    static int inited = 0;
    if (!inited) {
        cudaFuncSetAttribute(k_wmma<0>, cudaFuncAttributeMaxDynamicSharedMemorySize, GSM0_BYTES);
        cudaFuncSetAttribute(k_wmma<1>, cudaFuncAttributeMaxDynamicSharedMemorySize, GSM0_BYTES);
        cudaFuncSetAttribute(k_wmma<2>, cudaFuncAttributeMaxDynamicSharedMemorySize, GSM0_BYTES);
        cudaFuncSetAttribute(k_layer, cudaFuncAttributeMaxDynamicSharedMemorySize, LSM_BYTES);
        inited = 1;
    }

    k_pack<<<5736, 256>>>(w_skip, b_skip, w_post1, w_post2, w_sig, w_tanh, w_res);

    dim3 gin(LFULL / TT, BATCH);
    k_input<<<gin, 256>>>(x, w_in, b_in);

    int Lin = LFULL, Ls = LFULL;
    int flag = 0;
    for (int i = 0; i < NLAYER; i++) {
        int d = 1 << (i % 10);
        int Lout = Lin - d;
        int Lo_s = (Lout + 3) & ~3;
        dim3 g((Lout + TT2 - 1) / TT2, BATCH);
        k_layer<<<g, 256, LSM_BYTES>>>(flag, b_sig + i * 32, b_tanh + i * 32,
                                       b_res + i * 32, d, Lin, Ls, Lo_s, i);
        Lin = Lout;
        Ls = Lo_s;
        flag ^= 1;
    }

    const int NT = (FINALW + 127) / 128;  // 89
    k_wmma<0><<<dim3(4, NT, BATCH), 128, GSM0_BYTES>>>(nullptr, nullptr);
    k_wmma<1><<<dim3(4, NT, BATCH), 128, GSM0_BYTES>>>(b_post1, nullptr);
    k_wmma<2><<<dim3(2, NT, BATCH), 128, GSM0_BYTES>>>(b_post2, out);
}

// round 16
// speedup vs baseline: 1.1105x; 1.1105x over previous
#include <cuda_runtime.h>
#include <cuda_bf16.h>
#include <cuda_fp16.h>
#include <math.h>
#include <stdint.h>

#define NLAYER 50
#define BATCH 8
#define CIN 256
#define LFULL 16384
#define NRES 32
#define NSKIP 512
#define FINALW 11269
#define TT 128
#define TTP 132

// ---------------- scratch (static __device__, no allocs) ----------------
__device__ float g_buf0[(size_t)BATCH * NRES * LFULL];
__device__ float g_buf1[(size_t)BATCH * NRES * LFULL];
// activations: single fp16 planes, transposed [b][t][k]
__device__ __align__(16) __half g_gateT[(size_t)BATCH * FINALW * 1600];  // 288 MB
__device__ __align__(16) __half g_h1T[(size_t)BATCH * FINALW * 512];
__device__ __align__(16) __half g_h2T[(size_t)BATCH * FINALW * 512];
// GEMM weights: fp16 hi/lo planes [m][k]
__device__ __align__(16) __half g_A0hi[512 * 1600];
__device__ __align__(16) __half g_A0lo[512 * 1600];
__device__ __align__(16) __half g_A1hi[512 * 512];
__device__ __align__(16) __half g_A1lo[512 * 512];
__device__ __align__(16) __half g_A2hi[256 * 512];
__device__ __align__(16) __half g_A2lo[256 * 512];
// per-layer gate-conv weights [l][o(64)][k(64)] (o<32: sig, o>=32: tanh; k = c + 32*tap)
__device__ __align__(16) __nv_bfloat16 g_Wgh[NLAYER * 64 * 64];
__device__ __align__(16) __nv_bfloat16 g_Wgl[NLAYER * 64 * 64];
// per-layer res-conv weights [l][o(32)][c(32)]
__device__ __align__(16) __nv_bfloat16 g_Wrh[NLAYER * 32 * 32];
__device__ __align__(16) __nv_bfloat16 g_Wrl[NLAYER * 32 * 32];
__device__ float g_sumb[NSKIP];

// ---------------- helpers ----------------
__device__ __forceinline__ uint32_t smem_to_u32(const void* p) {
    uint32_t a;
    asm("{ .reg .u64 t; cvta.to.shared.u64 t, %1; cvt.u32.u64 %0, t; }" : "=r"(a) : "l"(p));
    return a;
}
__device__ __forceinline__ void ldsm4(uint32_t& r0, uint32_t& r1, uint32_t& r2, uint32_t& r3,
                                      uint32_t addr) {
    asm volatile("ldmatrix.sync.aligned.m8n8.x4.shared.b16 {%0,%1,%2,%3}, [%4];"
                 : "=r"(r0), "=r"(r1), "=r"(r2), "=r"(r3) : "r"(addr));
}
__device__ __forceinline__ void mma16816(float* c, const uint32_t* a, uint32_t b0, uint32_t b1) {
    asm volatile(
        "mma.sync.aligned.m16n8k16.row.col.f32.bf16.bf16.f32 "
        "{%0,%1,%2,%3}, {%4,%5,%6,%7}, {%8,%9}, {%0,%1,%2,%3};"
        : "+f"(c[0]), "+f"(c[1]), "+f"(c[2]), "+f"(c[3])
        : "r"(a[0]), "r"(a[1]), "r"(a[2]), "r"(a[3]), "r"(b0), "r"(b1));
}
__device__ __forceinline__ void mma16816h(float* c, const uint32_t* a, uint32_t b0, uint32_t b1) {
    asm volatile(
        "mma.sync.aligned.m16n8k16.row.col.f32.f16.f16.f32 "
        "{%0,%1,%2,%3}, {%4,%5,%6,%7}, {%8,%9}, {%0,%1,%2,%3};"
        : "+f"(c[0]), "+f"(c[1]), "+f"(c[2]), "+f"(c[3])
        : "r"(a[0]), "r"(a[1]), "r"(a[2]), "r"(a[3]), "r"(b0), "r"(b1));
}
__device__ __forceinline__ uint32_t cvt2(float a, float b) {
    uint32_t r;
    asm("cvt.rn.bf16x2.f32 %0, %1, %2;" : "=r"(r) : "f"(b), "f"(a));
    return r;
}
__device__ __forceinline__ uint32_t cvt2lo(float a, float b, uint32_t hi) {
    float ra = a - __uint_as_float(hi << 16);
    float rb = b - __uint_as_float(hi & 0xFFFF0000u);
    return cvt2(ra, rb);
}
// cp.async
__device__ __forceinline__ void cpa16(uint32_t dst, const void* src) {
    asm volatile("cp.async.cg.shared.global [%0], [%1], 16;" :: "r"(dst), "l"(src));
}
__device__ __forceinline__ void cpa16z(uint32_t dst, const void* src, bool pred) {
    int sz = pred ? 16 : 0;
    asm volatile("cp.async.cg.shared.global [%0], [%1], 16, %2;" :: "r"(dst), "l"(src),
                 "r"(sz));
}
#define CP_COMMIT() asm volatile("cp.async.commit_group;" ::: "memory")
#define CP_WAIT(N) asm volatile("cp.async.wait_group %0;" :: "n"(N) : "memory")
__device__ __forceinline__ float elu_f(float v) {
    return v > 0.f ? v : (__expf(v) - 1.f);
}

// ---------------- weight packing + bias pre-sum ----------------
__global__ void k_pack(const float* __restrict__ wsk, const float* __restrict__ bsk,
                       const float* __restrict__ w1, const float* __restrict__ w2,
                       const float* __restrict__ wsig, const float* __restrict__ wtanh,
                       const float* __restrict__ wres) {
    int idx = blockIdx.x * blockDim.x + threadIdx.x;
    const int T0 = 512 * 1600;
    if (idx < T0) {
        int m = idx / 1600, k = idx - m * 1600;
        float v = wsk[(size_t)(k >> 5) * (512 * 32) + m * 32 + (k & 31)];
        __half h = __float2half_rn(v);
        g_A0hi[idx] = h;
        g_A0lo[idx] = __float2half_rn(v - __half2float(h));
    }
    int i1 = idx - T0;
    if (i1 >= 0 && i1 < 512 * 512) {
        float v = w1[i1];
        __half h = __float2half_rn(v);
        g_A1hi[i1] = h;
        g_A1lo[i1] = __float2half_rn(v - __half2float(h));
    }
    int i2 = idx - T0 - 512 * 512;
    if (i2 >= 0 && i2 < 256 * 512) {
        float v = w2[i2];
        __half h = __float2half_rn(v);
        g_A2hi[i2] = h;
        g_A2lo[i2] = __float2half_rn(v - __half2float(h));
    }
    int i3 = idx - T0 - 512 * 512 - 256 * 512;
    if (i3 >= 0 && i3 < NLAYER * 64 * 64) {
        int l = i3 >> 12, rem = i3 & 4095;
        int o = rem >> 6, k = rem & 63;
        int c = k & 31, tap = k >> 5;
        float v = (o < 32) ? wsig[l * 2048 + o * 64 + c * 2 + tap]
                           : wtanh[l * 2048 + (o - 32) * 64 + c * 2 + tap];
        __nv_bfloat16 h = __float2bfloat16(v);
        g_Wgh[i3] = h;
        g_Wgl[i3] = __float2bfloat16(v - __bfloat162float(h));
    }
    int i4 = i3 - NLAYER * 64 * 64;
    if (i4 >= 0 && i4 < NLAYER * 32 * 32) {
        float v = wres[i4];
        __nv_bfloat16 h = __float2bfloat16(v);
        g_Wrh[i4] = h;
        g_Wrl[i4] = __float2bfloat16(v - __bfloat162float(h));
    }
    if (idx < 512) {
        float s = 0.f;
        for (int i = 0; i < NLAYER; i++) s += bsk[i * 512 + idx];
        g_sumb[idx] = s;
    }
}

// ---------------- input 1x1 conv: 256 -> 32 ----------------
__global__ __launch_bounds__(256) void k_input(const float* __restrict__ x,
                                               const float* __restrict__ w,
                                               const float* __restrict__ b) {
    __shared__ float sx[32][TT];
    __shared__ float sw[32][32];
    const int bb = blockIdx.y;
    const int t0 = blockIdx.x * TT;
    const int tid = threadIdx.x;
    const int o = tid & 31, tq = tid >> 5;
    const int tb = tq * 16;
    float acc[16];
    {
        float bo = b[o];
#pragma unroll
        for (int j = 0; j < 16; j++) acc[j] = bo;
    }
    for (int cc = 0; cc < CIN; cc += 32) {
        for (int idx = tid; idx < 32 * TT; idx += 256) {
            int c = idx >> 7, tt = idx & 127;
            sx[c][tt] = x[(size_t)(bb * CIN + cc + c) * LFULL + t0 + tt];
        }
        for (int idx = tid; idx < 1024; idx += 256) {
            int oo = idx & 31, c = idx >> 5;
            sw[c][oo] = w[oo * CIN + cc + c];
        }
        __syncthreads();
#pragma unroll 4
        for (int c = 0; c < 32; c++) {
            float wv = sw[c][o];
            const float2* ap = reinterpret_cast<const float2*>(&sx[c][tb]);
#pragma unroll
            for (int j2 = 0; j2 < 8; j2++) {
                float2 a = ap[j2];
                acc[2 * j2] += wv * a.x;
                acc[2 * j2 + 1] += wv * a.y;
            }
        }
        __syncthreads();
    }
#pragma unroll
    for (int j = 0; j < 16; j++) sx[o][(tb + j + o) & 127] = acc[j];
    __syncthreads();
    for (int idx = tid; idx < 32 * TT; idx += 256) {
        int c = idx >> 7, tt = idx & 127;
        g_buf0[(size_t)(bb * NRES + c) * LFULL + t0 + tt] = sx[c][(tt + c) & 127];
    }
}

// ---------------- one residual layer: all-mma, 1 block sync, cp.async loads ---------
#define SA0_B 0
#define SA1_B 16896
#define WGH_B 33792
#define WGL_B 43008
#define WRH_B 52224
#define WRL_B 56832
#define SBIAS_B 61440
#define LSM_BYTES 61824
__global__ __launch_bounds__(256, 3) void k_layer(int flag, const float* __restrict__ bsig,
                                                  const float* __restrict__ btanh,
                                                  const float* __restrict__ bres, int d,
                                                  int Lin, int Ls, int Lo_s, int layer) {
    const int Lout = Lin - d;
    const float* in = flag ? g_buf1 : g_buf0;
    float* outp = flag ? g_buf0 : g_buf1;
    extern __shared__ char smc[];
    float* sA0 = reinterpret_cast<float*>(smc + SA0_B);
    float* sA1 = reinterpret_cast<float*>(smc + SA1_B);
    float* sBias = reinterpret_cast<float*>(smc + SBIAS_B);
    const uint32_t smem_u = smem_to_u32(smc);
    const int b = blockIdx.y;
    const int t0 = blockIdx.x * TT;
    const int tid = threadIdx.x;

    // gate/res weights -> smem via cp.async (row stride 144B)
    {
        const __nv_bfloat16* Wh = g_Wgh + layer * 4096;
        const __nv_bfloat16* Wl = g_Wgl + layer * 4096;
        for (int i = tid; i < 512; i += 256) {
            int row = i >> 3, ch = i & 7;
            uint32_t so = (uint32_t)(row * 144 + ch * 16);
            cpa16(smem_u + WGH_B + so, Wh + row * 64 + ch * 8);
            cpa16(smem_u + WGL_B + so, Wl + row * 64 + ch * 8);
        }
        const __nv_bfloat16* Rh = g_Wrh + layer * 1024;
        const __nv_bfloat16* Rl = g_Wrl + layer * 1024;
        if (tid < 128) {
            int row = tid >> 2, ch = tid & 3;
            uint32_t so = (uint32_t)(row * 144 + ch * 16);
            cpa16(smem_u + WRH_B + so, Rh + row * 32 + ch * 8);
            cpa16(smem_u + WRL_B + so, Rl + row * 32 + ch * 8);
        }
    }
    if (tid < 32) {
        sBias[tid] = bsig[tid];
        sBias[32 + tid] = btanh[tid];
        sBias[64 + tid] = bres[tid];
    }
    const float* inb = in + (size_t)b * NRES * Ls;
    const bool fulltile = (t0 + TT <= Lout);
    if (fulltile) {
        if ((d & 3) == 0) {
            // both taps 16B-aligned -> fully async
            for (int idx = tid; idx < 1024; idx += 256) {
                int c = idx >> 5, q = idx & 31;
                int t = t0 + 4 * q;
                const float* r = inb + (size_t)c * Ls;
                uint32_t so = (uint32_t)(c * (TTP * 4) + 16 * q);
                cpa16(smem_u + SA0_B + so, r + t);
                cpa16(smem_u + SA1_B + so, r + t + d);
            }
        } else {
            for (int idx = tid; idx < 1024; idx += 256) {
                int c = idx >> 5, q = idx & 31;
                int t = t0 + 4 * q;
                const float* r = inb + (size_t)c * Ls;
                uint32_t so = (uint32_t)(c * (TTP * 4) + 16 * q);
                cpa16(smem_u + SA0_B + so, r + t);
                float4 v1;
                v1.x = r[t + d + 0];
                v1.y = r[t + d + 1];
                v1.z = r[t + d + 2];
                v1.w = r[t + d + 3];
                *reinterpret_cast<float4*>(&sA1[c * TTP + 4 * q]) = v1;
            }
        }
    } else {
        for (int idx = tid; idx < 1024; idx += 256) {
            int c = idx >> 5, q = idx & 31;
            int t = t0 + 4 * q;
            const float* r = inb + (size_t)c * Ls;
            float4 v0, v1;
            v0.x = (t + 0 < Lin) ? r[t + 0] : 0.f;
            v0.y = (t + 1 < Lin) ? r[t + 1] : 0.f;
            v0.z = (t + 2 < Lin) ? r[t + 2] : 0.f;
            v0.w = (t + 3 < Lin) ? r[t + 3] : 0.f;
            v1.x = (t + 0 < Lout) ? r[t + d + 0] : 0.f;
            v1.y = (t + 1 < Lout) ? r[t + d + 1] : 0.f;
            v1.z = (t + 2 < Lout) ? r[t + d + 2] : 0.f;
            v1.w = (t + 3 < Lout) ? r[t + d + 3] : 0.f;
            *reinterpret_cast<float4*>(&sA0[c * TTP + 4 * q]) = v0;
            *reinterpret_cast<float4*>(&sA1[c * TTP + 4 * q]) = v1;
        }
    }
    CP_COMMIT();
    CP_WAIT(0);
    __syncthreads();  // ---- the ONLY block sync

    const int w = tid >> 5, lane = tid & 31;
    const int g = lane >> 2, tc = lane & 3;
    const int tl = (w << 4) + g;
    float acc[8][4];
#pragma unroll
    for (int ni = 0; ni < 8; ni++)
#pragma unroll
        for (int e = 0; e < 4; e++) acc[ni][e] = 0.f;

    const uint32_t bpair = (uint32_t)((((lane >> 4) & 1) * 8 + (lane & 7)) * 144 +
                                      ((lane >> 3) & 1) * 16);

#pragma unroll
    for (int s = 0; s < 4; s++) {
        const float* sp = (s < 2) ? sA0 : sA1;
        const int cb = ((s & 1) << 4) + (tc << 1);
        float x00 = sp[cb * TTP + tl], x01 = sp[(cb + 1) * TTP + tl];
        float x10 = sp[cb * TTP + tl + 8], x11 = sp[(cb + 1) * TTP + tl + 8];
        float x20 = sp[(cb + 8) * TTP + tl], x21 = sp[(cb + 9) * TTP + tl];
        float x30 = sp[(cb + 8) * TTP + tl + 8], x31 = sp[(cb + 9) * TTP + tl + 8];
        uint32_t ahi[4], alo[4];
        ahi[0] = cvt2(x00, x01); alo[0] = cvt2lo(x00, x01, ahi[0]);
        ahi[1] = cvt2(x10, x11); alo[1] = cvt2lo(x10, x11, ahi[1]);
        ahi[2] = cvt2(x20, x21); alo[2] = cvt2lo(x20, x21, ahi[2]);
        ahi[3] = cvt2(x30, x31); alo[3] = cvt2lo(x30, x31, ahi[3]);
#pragma unroll
        for (int ni2 = 0; ni2 < 4; ni2++) {
            uint32_t ro = smem_u + bpair + (uint32_t)(ni2 * 16 * 144 + s * 32);
            uint32_t e0, e1, o0, o1, f0, f1, p0, p1;
            ldsm4(e0, e1, o0, o1, ro + WGH_B);
            ldsm4(f0, f1, p0, p1, ro + WGL_B);
            mma16816(acc[2 * ni2], ahi, e0, e1);
            mma16816(acc[2 * ni2], alo, e0, e1);
            mma16816(acc[2 * ni2], ahi, f0, f1);
            mma16816(acc[2 * ni2 + 1], ahi, o0, o1);
            mma16816(acc[2 * ni2 + 1], alo, o0, o1);
            mma16816(acc[2 * ni2 + 1], ahi, p0, p1);
        }
    }

    float gate[4][4];
#pragma unroll
    for (int ni = 0; ni < 4; ni++) {
        int n0 = ni * 8 + 2 * tc;
        float bs0 = sBias[n0], bs1 = sBias[n0 + 1];
        float bt0 = sBias[32 + n0], bt1 = sBias[32 + n0 + 1];
#pragma unroll
        for (int h = 0; h < 2; h++) {
            float ds0 = acc[ni][2 * h] + bs0, dt0 = acc[ni + 4][2 * h] + bt0;
            float ds1 = acc[ni][2 * h + 1] + bs1, dt1 = acc[ni + 4][2 * h + 1] + bt1;
            float s0 = __fdividef(1.f, 1.f + __expf(-ds0));
            float s1 = __fdividef(1.f, 1.f + __expf(-ds1));
            float th0 = 1.f - __fdividef(2.f, __expf(2.f * dt0) + 1.f);
            float th1 = 1.f - __fdividef(2.f, __expf(2.f * dt1) + 1.f);
            gate[ni][2 * h] = s0 * th0;
            gate[ni][2 * h + 1] = s1 * th1;
        }
    }

    float racc[4][4];
#pragma unroll
    for (int ot = 0; ot < 4; ot++) {
        int n0 = ot * 8 + 2 * tc;
        racc[ot][0] = sBias[64 + n0];
        racc[ot][1] = sBias[64 + n0 + 1];
        racc[ot][2] = racc[ot][0];
        racc[ot][3] = racc[ot][1];
    }
#pragma unroll
    for (int kk = 0; kk < 2; kk++) {
        uint32_t ah[4], al[4];
        ah[0] = cvt2(gate[2 * kk][0], gate[2 * kk][1]);
        al[0] = cvt2lo(gate[2 * kk][0], gate[2 * kk][1], ah[0]);
        ah[1] = cvt2(gate[2 * kk][2], gate[2 * kk][3]);
        al[1] = cvt2lo(gate[2 * kk][2], gate[2 * kk][3], ah[1]);
        ah[2] = cvt2(gate[2 * kk + 1][0], gate[2 * kk + 1][1]);
        al[2] = cvt2lo(gate[2 * kk + 1][0], gate[2 * kk + 1][1], ah[2]);
        ah[3] = cvt2(gate[2 * kk + 1][2], gate[2 * kk + 1][3]);
        al[3] = cvt2lo(gate[2 * kk + 1][2], gate[2 * kk + 1][3], ah[3]);
#pragma unroll
        for (int ot2 = 0; ot2 < 2; ot2++) {
            uint32_t ro = smem_u + bpair + (uint32_t)(ot2 * 16 * 144 + kk * 32);
            uint32_t e0, e1, o0, o1, f0, f1, p0, p1;
            ldsm4(e0, e1, o0, o1, ro + WRH_B);
            ldsm4(f0, f1, p0, p1, ro + WRL_B);
            mma16816(racc[2 * ot2], ah, e0, e1);
            mma16816(racc[2 * ot2], al, e0, e1);
            mma16816(racc[2 * ot2], ah, f0, f1);
            mma16816(racc[2 * ot2 + 1], ah, o0, o1);
            mma16816(racc[2 * ot2 + 1], al, o0, o1);
            mma16816(racc[2 * ot2 + 1], ah, p0, p1);
        }
    }

#pragma unroll
    for (int ni = 0; ni < 4; ni++) {
        int n0 = ni * 8 + 2 * tc;
#pragma unroll
        for (int h = 0; h < 2; h++) {
            int t = tl + 8 * h;
            sA0[n0 * TTP + t] = gate[ni][2 * h];
            sA0[(n0 + 1) * TTP + t] = gate[ni][2 * h + 1];
        }
    }

    {
        float* outb = outp + (size_t)b * NRES * Lo_s;
#pragma unroll
        for (int ot = 0; ot < 4; ot++) {
            int cbase = ot * 8 + 2 * tc;
#pragma unroll
            for (int h = 0; h < 2; h++) {
                int t = t0 + tl + 8 * h;
                if (t < Lout) {
                    float a0 = sA1[cbase * TTP + tl + 8 * h];
                    float a1 = sA1[(cbase + 1) * TTP + tl + 8 * h];
                    outb[(size_t)cbase * Lo_s + t] = racc[ot][2 * h] + a0;
                    outb[(size_t)(cbase + 1) * Lo_s + t] = racc[ot][2 * h + 1] + a1;
                }
            }
        }
    }
    __syncwarp();

    // gate -> single fp16 plane [b][t][layer*32 + c]
    const int off = Lout - FINALW;
#pragma unroll
    for (int k = 0; k < 8; k++) {
        int idx = lane + 32 * k;
        int ttl = idx >> 4, cp = idx & 15;
        int tt = (w << 4) + ttl;
        int t = t0 + tt;
        if (t < Lout && t >= off) {
            int c2 = 2 * cp;
            float v0 = sA0[c2 * TTP + tt];
            float v1 = sA0[(c2 + 1) * TTP + tt];
            size_t oo = ((size_t)b * FINALW + (t - off)) * 1600 + layer * 32 + c2;
            *reinterpret_cast<__half2*>(g_gateT + oo) = __floats2half2_rn(v0, v1);
        }
    }
}

// ---- unified fp16 2-term GEMM: C = (Ah + Al) * B, CTA 128m x 128n, 4 warps ----
#define LROW2 80
#define A_LO_OFF0 10240
#define B_OFF0 20480
#define STAGE0 30720
#define GSM0_BYTES 67584
template <int MODE>
__global__ __launch_bounds__(128, 2) void k_wmma(const float* __restrict__ bias_in,
                                                 float* __restrict__ Cext) {
    constexpr int K = (MODE == 0) ? 1600 : 512;
    constexpr int NC = K / 32;
    const __half* Ahi = (MODE == 0) ? g_A0hi : (MODE == 1) ? g_A1hi : g_A2hi;
    const __half* Alo = (MODE == 0) ? g_A0lo : (MODE == 1) ? g_A1lo : g_A2lo;
    const __half* Bp = (MODE == 0) ? g_gateT : (MODE == 1) ? g_h1T : g_h2T;

    extern __shared__ char smem[];
    const uint32_t smem_u = smem_to_u32(smem);
    const int tid = threadIdx.x, wid = tid >> 5, lane = tid & 31;
    const int m0 = blockIdx.x * 128;
    const int t0 = blockIdx.y * 128;
    const int b = blockIdx.z;
    const int wm = (wid >> 1) * 64, wn = (wid & 1) * 64;

    const __half* Brp = Bp + (size_t)b * FINALW * K;

    float acc[4][8][4];
#pragma unroll
    for (int mi = 0; mi < 4; mi++)
#pragma unroll
        for (int ni = 0; ni < 8; ni++)
#pragma unroll
            for (int e = 0; e < 4; e++) acc[mi][ni][e] = 0.f;

    const uint32_t rA4 = (wm + (lane & 15)) * LROW2 + (lane >> 4) * 16;
    const uint32_t rB4 = B_OFF0 + (wn + ((lane >> 4) & 1) * 8 + (lane & 7)) * LROW2 +
                         ((lane >> 3) & 1) * 16;

    const int lrow = tid >> 2, lunit = tid & 3;

    auto load_chunk = [&](int ch, int buf) {
        const uint32_t st = smem_u + buf * STAGE0;
        const int k0 = ch * 32;
#pragma unroll
        for (int i = 0; i < 4; i++) {
            int r = lrow + 32 * i;
            uint32_t soff = (uint32_t)(r * LROW2 + lunit * 16);
            size_t aoff = (size_t)(m0 + r) * K + k0 + lunit * 8;
            cpa16(st + soff, Ahi + aoff);
            cpa16(st + A_LO_OFF0 + soff, Alo + aoff);
            int t = t0 + r;
            bool pr = t < FINALW;
            int tcl = pr ? t : (FINALW - 1);
            cpa16z(st + B_OFF0 + soff, Brp + (size_t)tcl * K + k0 + lunit * 8, pr);
        }
        CP_COMMIT();
    };

    load_chunk(0, 0);
    for (int ch = 0; ch < NC; ch++) {
        if (ch + 1 < NC) {
            load_chunk(ch + 1, (ch + 1) & 1);
            CP_WAIT(1);
        } else {
            CP_WAIT(0);
        }
        __syncthreads();
        const uint32_t base = smem_u + (ch & 1) * STAGE0;
        const uint32_t aAh = base + rA4, aAl = aAh + A_LO_OFF0;
        const uint32_t aB4 = base + rB4;
#pragma unroll
        for (int k16 = 0; k16 < 2; k16++) {
            uint32_t ah[4][4], al[4][4];
#pragma unroll
            for (int mi = 0; mi < 4; mi++) {
                ldsm4(ah[mi][0], ah[mi][1], ah[mi][2], ah[mi][3],
                      aAh + mi * (16 * LROW2) + k16 * 32);
                ldsm4(al[mi][0], al[mi][1], al[mi][2], al[mi][3],
                      aAl + mi * (16 * LROW2) + k16 * 32);
            }
#pragma unroll
            for (int ni2 = 0; ni2 < 4; ni2++) {
                uint32_t e0, e1, o0, o1;
                ldsm4(e0, e1, o0, o1, aB4 + ni2 * (16 * LROW2) + k16 * 32);
#pragma unroll
                for (int mi = 0; mi < 4; mi++) {
                    mma16816h(acc[mi][2 * ni2], ah[mi], e0, e1);
                    mma16816h(acc[mi][2 * ni2], al[mi], e0, e1);
                    mma16816h(acc[mi][2 * ni2 + 1], ah[mi], o0, o1);
                    mma16816h(acc[mi][2 * ni2 + 1], al[mi], o0, o1);
                }
            }
        }
        __syncthreads();
    }

    // ---- epilogue ----
    const int g = lane >> 2, tig = lane & 3;
    const float* bias = (MODE == 0) ? g_sumb : bias_in;
    float bv[4][2];
#pragma unroll
    for (int mi = 0; mi < 4; mi++)
#pragma unroll
        for (int h = 0; h < 2; h++) bv[mi][h] = bias[m0 + wm + mi * 16 + g + 8 * h];

    if (MODE == 2) {
#pragma unroll
        for (int mi = 0; mi < 4; mi++)
#pragma unroll
            for (int ni = 0; ni < 8; ni++)
#pragma unroll
                for (int h = 0; h < 2; h++)
#pragma unroll
                    for (int p = 0; p < 2; p++) {
                        int t = t0 + wn + ni * 8 + 2 * tig + p;
                        if (t < FINALW) {
                            int m = m0 + wm + mi * 16 + g + 8 * h;
                            Cext[((size_t)b * 256 + m) * FINALW + t] =
                                acc[mi][ni][h * 2 + p] + bv[mi][h];
                        }
                    }
        return;
    }

    __syncthreads();
    float* sT = reinterpret_cast<float*>(smem);  // [128 n][132]
#pragma unroll
    for (int mi = 0; mi < 4; mi++)
#pragma unroll
        for (int ni = 0; ni < 8; ni++)
#pragma unroll
            for (int h = 0; h < 2; h++)
#pragma unroll
                for (int p = 0; p < 2; p++) {
                    float v = elu_f(acc[mi][ni][h * 2 + p] + bv[mi][h]);
                    int n = wn + ni * 8 + 2 * tig + p;
                    int m = wm + mi * 16 + g + 8 * h;
                    sT[n * 132 + m] = v;
                }
    __syncthreads();
    __half* Op = (MODE == 0) ? g_h1T : g_h2T;
    for (int idx = tid; idx < 128 * 64; idx += 128) {
        int t = idx >> 6, mp = idx & 63;
        int tg = t0 + t;
        if (tg < FINALW) {
            float v0 = sT[t * 132 + 2 * mp];
            float v1 = sT[t * 132 + 2 * mp + 1];
            size_t o = ((size_t)b * FINALW + tg) * 512 + m0 + 2 * mp;
            *reinterpret_cast<__half2*>(Op + o) = __floats2half2_rn(v0, v1);
        }
    }
}

// ---------------- launch ----------------
extern "C" void kernel_launch(void* const* d_in, const int* in_sizes, int n_in,
                              void* d_out, int out_size) {
    (void)in_sizes; (void)n_in; (void)out_size;
    const float* x = (const float*)d_in[0];
    const float* w_in = (const float*)d_in[1];
    const float* b_in = (const float*)d_in[2];
    const float* w_sig = (const float*)d_in[3];
    const float* b_sig = (const float*)d_in[4];
    const float* w_tanh = (const float*)d_in[5];
    const float* b_tanh = (const float*)d_in[6];
    const float* w_skip = (const float*)d_in[7];
    const float* b_skip = (const float*)d_in[8];
    const float* w_res = (const float*)d_in[9];
    const float* b_res = (const float*)d_in[10];
    const float* w_post1 = (const float*)d_in[11];
    const float* b_post1 = (const float*)d_in[12];
    const float* w_post2 = (const float*)d_in[13];
    const float* b_post2 = (const float*)d_in[14];
    float* out = (float*)d_out;

    static int inited = 0;
    if (!inited) {
        cudaFuncSetAttribute(k_wmma<0>, cudaFuncAttributeMaxDynamicSharedMemorySize, GSM0_BYTES);
        cudaFuncSetAttribute(k_wmma<1>, cudaFuncAttributeMaxDynamicSharedMemorySize, GSM0_BYTES);
        cudaFuncSetAttribute(k_wmma<2>, cudaFuncAttributeMaxDynamicSharedMemorySize, GSM0_BYTES);
        cudaFuncSetAttribute(k_layer, cudaFuncAttributeMaxDynamicSharedMemorySize, LSM_BYTES);
        inited = 1;
    }

    k_pack<<<5736, 256>>>(w_skip, b_skip, w_post1, w_post2, w_sig, w_tanh, w_res);

    dim3 gin(LFULL / TT, BATCH);
    k_input<<<gin, 256>>>(x, w_in, b_in);

    int Lin = LFULL, Ls = LFULL;
    int flag = 0;
    for (int i = 0; i < NLAYER; i++) {
        int d = 1 << (i % 10);
        int Lout = Lin - d;
        int Lo_s = (Lout + 3) & ~3;
        dim3 g((Lout + TT - 1) / TT, BATCH);
        k_layer<<<g, 256, LSM_BYTES>>>(flag, b_sig + i * 32, b_tanh + i * 32,
                                       b_res + i * 32, d, Lin, Ls, Lo_s, i);
        Lin = Lout;
        Ls = Lo_s;
        flag ^= 1;
    }

    const int NT = (FINALW + 127) / 128;  // 89
    k_wmma<0><<<dim3(4, NT, BATCH), 128, GSM0_BYTES>>>(nullptr, nullptr);
    k_wmma<1><<<dim3(4, NT, BATCH), 128, GSM0_BYTES>>>(b_post1, nullptr);
    k_wmma<2><<<dim3(2, NT, BATCH), 128, GSM0_BYTES>>>(b_post2, out);
}

// round 17
// speedup vs baseline: 1.3071x; 1.1771x over previous
#include <cuda_runtime.h>
#include <cuda_bf16.h>
#include <cuda_fp16.h>
#include <math.h>
#include <stdint.h>

#define NLAYER 50
#define BATCH 8
#define CIN 256
#define LFULL 16384
#define NRES 32
#define NSKIP 512
#define FINALW 11269
#define TT 128
#define TTP 132

// ---------------- scratch (static __device__, no allocs) ----------------
__device__ float g_buf0[(size_t)BATCH * NRES * LFULL];
__device__ float g_buf1[(size_t)BATCH * NRES * LFULL];
// activations: single fp16 planes, transposed [b][t][k]
__device__ __align__(16) __half g_gateT[(size_t)BATCH * FINALW * 1600];  // 288 MB
__device__ __align__(16) __half g_h1T[(size_t)BATCH * FINALW * 512];
__device__ __align__(16) __half g_h2T[(size_t)BATCH * FINALW * 512];
// GEMM weights: fp16 hi/lo planes [m][k]
__device__ __align__(16) __half g_A0hi[512 * 1600];
__device__ __align__(16) __half g_A0lo[512 * 1600];
__device__ __align__(16) __half g_A1hi[512 * 512];
__device__ __align__(16) __half g_A1lo[512 * 512];
__device__ __align__(16) __half g_A2hi[256 * 512];
__device__ __align__(16) __half g_A2lo[256 * 512];
// per-layer gate-conv weights [l][o(64)][k(64)] (o<32: sig, o>=32: tanh; k = c + 32*tap)
__device__ __align__(16) __nv_bfloat16 g_Wgh[NLAYER * 64 * 64];
__device__ __align__(16) __nv_bfloat16 g_Wgl[NLAYER * 64 * 64];
// per-layer res-conv weights [l][o(32)][c(32)]
__device__ __align__(16) __nv_bfloat16 g_Wrh[NLAYER * 32 * 32];
__device__ __align__(16) __nv_bfloat16 g_Wrl[NLAYER * 32 * 32];
__device__ float g_sumb[NSKIP];

// ---------------- helpers ----------------
__device__ __forceinline__ uint32_t smem_to_u32(const void* p) {
    uint32_t a;
    asm("{ .reg .u64 t; cvta.to.shared.u64 t, %1; cvt.u32.u64 %0, t; }" : "=r"(a) : "l"(p));
    return a;
}
__device__ __forceinline__ void ldsm4(uint32_t& r0, uint32_t& r1, uint32_t& r2, uint32_t& r3,
                                      uint32_t addr) {
    asm volatile("ldmatrix.sync.aligned.m8n8.x4.shared.b16 {%0,%1,%2,%3}, [%4];"
                 : "=r"(r0), "=r"(r1), "=r"(r2), "=r"(r3) : "r"(addr));
}
__device__ __forceinline__ void mma16816(float* c, const uint32_t* a, uint32_t b0, uint32_t b1) {
    asm volatile(
        "mma.sync.aligned.m16n8k16.row.col.f32.bf16.bf16.f32 "
        "{%0,%1,%2,%3}, {%4,%5,%6,%7}, {%8,%9}, {%0,%1,%2,%3};"
        : "+f"(c[0]), "+f"(c[1]), "+f"(c[2]), "+f"(c[3])
        : "r"(a[0]), "r"(a[1]), "r"(a[2]), "r"(a[3]), "r"(b0), "r"(b1));
}
__device__ __forceinline__ void mma16816h(float* c, const uint32_t* a, uint32_t b0, uint32_t b1) {
    asm volatile(
        "mma.sync.aligned.m16n8k16.row.col.f32.f16.f16.f32 "
        "{%0,%1,%2,%3}, {%4,%5,%6,%7}, {%8,%9}, {%0,%1,%2,%3};"
        : "+f"(c[0]), "+f"(c[1]), "+f"(c[2]), "+f"(c[3])
        : "r"(a[0]), "r"(a[1]), "r"(a[2]), "r"(a[3]), "r"(b0), "r"(b1));
}
__device__ __forceinline__ uint32_t cvt2(float a, float b) {
    uint32_t r;
    asm("cvt.rn.bf16x2.f32 %0, %1, %2;" : "=r"(r) : "f"(b), "f"(a));
    return r;
}
__device__ __forceinline__ uint32_t cvt2lo(float a, float b, uint32_t hi) {
    float ra = a - __uint_as_float(hi << 16);
    float rb = b - __uint_as_float(hi & 0xFFFF0000u);
    return cvt2(ra, rb);
}
// cp.async
__device__ __forceinline__ void cpa16(uint32_t dst, const void* src) {
    asm volatile("cp.async.cg.shared.global [%0], [%1], 16;" :: "r"(dst), "l"(src));
}
__device__ __forceinline__ void cpa16z(uint32_t dst, const void* src, bool pred) {
    int sz = pred ? 16 : 0;
    asm volatile("cp.async.cg.shared.global [%0], [%1], 16, %2;" :: "r"(dst), "l"(src),
                 "r"(sz));
}
#define CP_COMMIT() asm volatile("cp.async.commit_group;" ::: "memory")
#define CP_WAIT(N) asm volatile("cp.async.wait_group %0;" :: "n"(N) : "memory")
__device__ __forceinline__ float elu_f(float v) {
    return v > 0.f ? v : (__expf(v) - 1.f);
}

// ---------------- weight packing + bias pre-sum ----------------
__global__ void k_pack(const float* __restrict__ wsk, const float* __restrict__ bsk,
                       const float* __restrict__ w1, const float* __restrict__ w2,
                       const float* __restrict__ wsig, const float* __restrict__ wtanh,
                       const float* __restrict__ wres) {
    int idx = blockIdx.x * blockDim.x + threadIdx.x;
    const int T0 = 512 * 1600;
    if (idx < T0) {
        int m = idx / 1600, k = idx - m * 1600;
        float v = wsk[(size_t)(k >> 5) * (512 * 32) + m * 32 + (k & 31)];
        __half h = __float2half_rn(v);
        g_A0hi[idx] = h;
        g_A0lo[idx] = __float2half_rn(v - __half2float(h));
    }
    int i1 = idx - T0;
    if (i1 >= 0 && i1 < 512 * 512) {
        float v = w1[i1];
        __half h = __float2half_rn(v);
        g_A1hi[i1] = h;
        g_A1lo[i1] = __float2half_rn(v - __half2float(h));
    }
    int i2 = idx - T0 - 512 * 512;
    if (i2 >= 0 && i2 < 256 * 512) {
        float v = w2[i2];
        __half h = __float2half_rn(v);
        g_A2hi[i2] = h;
        g_A2lo[i2] = __float2half_rn(v - __half2float(h));
    }
    int i3 = idx - T0 - 512 * 512 - 256 * 512;
    if (i3 >= 0 && i3 < NLAYER * 64 * 64) {
        int l = i3 >> 12, rem = i3 & 4095;
        int o = rem >> 6, k = rem & 63;
        int c = k & 31, tap = k >> 5;
        float v = (o < 32) ? wsig[l * 2048 + o * 64 + c * 2 + tap]
                           : wtanh[l * 2048 + (o - 32) * 64 + c * 2 + tap];
        __nv_bfloat16 h = __float2bfloat16(v);
        g_Wgh[i3] = h;
        g_Wgl[i3] = __float2bfloat16(v - __bfloat162float(h));
    }
    int i4 = i3 - NLAYER * 64 * 64;
    if (i4 >= 0 && i4 < NLAYER * 32 * 32) {
        float v = wres[i4];
        __nv_bfloat16 h = __float2bfloat16(v);
        g_Wrh[i4] = h;
        g_Wrl[i4] = __float2bfloat16(v - __bfloat162float(h));
    }
    if (idx < 512) {
        float s = 0.f;
        for (int i = 0; i < NLAYER; i++) s += bsk[i * 512 + idx];
        g_sumb[idx] = s;
    }
}

// ---------------- input 1x1 conv: 256 -> 32 ----------------
__global__ __launch_bounds__(256) void k_input(const float* __restrict__ x,
                                               const float* __restrict__ w,
                                               const float* __restrict__ b) {
    __shared__ float sx[32][TT];
    __shared__ float sw[32][32];
    const int bb = blockIdx.y;
    const int t0 = blockIdx.x * TT;
    const int tid = threadIdx.x;
    const int o = tid & 31, tq = tid >> 5;
    const int tb = tq * 16;
    float acc[16];
    {
        float bo = b[o];
#pragma unroll
        for (int j = 0; j < 16; j++) acc[j] = bo;
    }
    for (int cc = 0; cc < CIN; cc += 32) {
        for (int idx = tid; idx < 32 * TT; idx += 256) {
            int c = idx >> 7, tt = idx & 127;
            sx[c][tt] = x[(size_t)(bb * CIN + cc + c) * LFULL + t0 + tt];
        }
        for (int idx = tid; idx < 1024; idx += 256) {
            int oo = idx & 31, c = idx >> 5;
            sw[c][oo] = w[oo * CIN + cc + c];
        }
        __syncthreads();
#pragma unroll 4
        for (int c = 0; c < 32; c++) {
            float wv = sw[c][o];
            const float2* ap = reinterpret_cast<const float2*>(&sx[c][tb]);
#pragma unroll
            for (int j2 = 0; j2 < 8; j2++) {
                float2 a = ap[j2];
                acc[2 * j2] += wv * a.x;
                acc[2 * j2 + 1] += wv * a.y;
            }
        }
        __syncthreads();
    }
#pragma unroll
    for (int j = 0; j < 16; j++) sx[o][(tb + j + o) & 127] = acc[j];
    __syncthreads();
    for (int idx = tid; idx < 32 * TT; idx += 256) {
        int c = idx >> 7, tt = idx & 127;
        g_buf0[(size_t)(bb * NRES + c) * LFULL + t0 + tt] = sx[c][(tt + c) & 127];
    }
}

// ---------------- one residual layer: all-mma, 1 block sync, cp.async loads ---------
#define SA0_B 0
#define SA1_B 16896
#define WGH_B 33792
#define WGL_B 43008
#define WRH_B 52224
#define WRL_B 56832
#define SBIAS_B 61440
#define LSM_BYTES 61824
__global__ __launch_bounds__(256, 3) void k_layer(int flag, const float* __restrict__ bsig,
                                                  const float* __restrict__ btanh,
                                                  const float* __restrict__ bres, int d,
                                                  int Lin, int Ls, int Lo_s, int layer) {
    const int Lout = Lin - d;
    const float* in = flag ? g_buf1 : g_buf0;
    float* outp = flag ? g_buf0 : g_buf1;
    extern __shared__ char smc[];
    float* sA0 = reinterpret_cast<float*>(smc + SA0_B);
    float* sA1 = reinterpret_cast<float*>(smc + SA1_B);
    float* sBias = reinterpret_cast<float*>(smc + SBIAS_B);
    const uint32_t smem_u = smem_to_u32(smc);
    const int b = blockIdx.y;
    const int t0 = blockIdx.x * TT;
    const int tid = threadIdx.x;

    // gate/res weights -> smem via cp.async (row stride 144B)
    {
        const __nv_bfloat16* Wh = g_Wgh + layer * 4096;
        const __nv_bfloat16* Wl = g_Wgl + layer * 4096;
        for (int i = tid; i < 512; i += 256) {
            int row = i >> 3, ch = i & 7;
            uint32_t so = (uint32_t)(row * 144 + ch * 16);
            cpa16(smem_u + WGH_B + so, Wh + row * 64 + ch * 8);
            cpa16(smem_u + WGL_B + so, Wl + row * 64 + ch * 8);
        }
        const __nv_bfloat16* Rh = g_Wrh + layer * 1024;
        const __nv_bfloat16* Rl = g_Wrl + layer * 1024;
        if (tid < 128) {
            int row = tid >> 2, ch = tid & 3;
            uint32_t so = (uint32_t)(row * 144 + ch * 16);
            cpa16(smem_u + WRH_B + so, Rh + row * 32 + ch * 8);
            cpa16(smem_u + WRL_B + so, Rl + row * 32 + ch * 8);
        }
    }
    if (tid < 32) {
        sBias[tid] = bsig[tid];
        sBias[32 + tid] = btanh[tid];
        sBias[64 + tid] = bres[tid];
    }
    const float* inb = in + (size_t)b * NRES * Ls;
    const bool fulltile = (t0 + TT <= Lout);
    if (fulltile) {
        if ((d & 3) == 0) {
            for (int idx = tid; idx < 1024; idx += 256) {
                int c = idx >> 5, q = idx & 31;
                int t = t0 + 4 * q;
                const float* r = inb + (size_t)c * Ls;
                uint32_t so = (uint32_t)(c * (TTP * 4) + 16 * q);
                cpa16(smem_u + SA0_B + so, r + t);
                cpa16(smem_u + SA1_B + so, r + t + d);
            }
        } else {
            for (int idx = tid; idx < 1024; idx += 256) {
                int c = idx >> 5, q = idx & 31;
                int t = t0 + 4 * q;
                const float* r = inb + (size_t)c * Ls;
                uint32_t so = (uint32_t)(c * (TTP * 4) + 16 * q);
                cpa16(smem_u + SA0_B + so, r + t);
                float4 v1;
                v1.x = r[t + d + 0];
                v1.y = r[t + d + 1];
                v1.z = r[t + d + 2];
                v1.w = r[t + d + 3];
                *reinterpret_cast<float4*>(&sA1[c * TTP + 4 * q]) = v1;
            }
        }
    } else {
        for (int idx = tid; idx < 1024; idx += 256) {
            int c = idx >> 5, q = idx & 31;
            int t = t0 + 4 * q;
            const float* r = inb + (size_t)c * Ls;
            float4 v0, v1;
            v0.x = (t + 0 < Lin) ? r[t + 0] : 0.f;
            v0.y = (t + 1 < Lin) ? r[t + 1] : 0.f;
            v0.z = (t + 2 < Lin) ? r[t + 2] : 0.f;
            v0.w = (t + 3 < Lin) ? r[t + 3] : 0.f;
            v1.x = (t + 0 < Lout) ? r[t + d + 0] : 0.f;
            v1.y = (t + 1 < Lout) ? r[t + d + 1] : 0.f;
            v1.z = (t + 2 < Lout) ? r[t + d + 2] : 0.f;
            v1.w = (t + 3 < Lout) ? r[t + d + 3] : 0.f;
            *reinterpret_cast<float4*>(&sA0[c * TTP + 4 * q]) = v0;
            *reinterpret_cast<float4*>(&sA1[c * TTP + 4 * q]) = v1;
        }
    }
    CP_COMMIT();
    CP_WAIT(0);
    __syncthreads();  // ---- the ONLY block sync

    const int w = tid >> 5, lane = tid & 31;
    const int g = lane >> 2, tc = lane & 3;
    const int tl = (w << 4) + g;
    float acc[8][4];
#pragma unroll
    for (int ni = 0; ni < 8; ni++)
#pragma unroll
        for (int e = 0; e < 4; e++) acc[ni][e] = 0.f;

    const uint32_t bpair = (uint32_t)((((lane >> 4) & 1) * 8 + (lane & 7)) * 144 +
                                      ((lane >> 3) & 1) * 16);

#pragma unroll
    for (int s = 0; s < 4; s++) {
        const float* sp = (s < 2) ? sA0 : sA1;
        const int cb = ((s & 1) << 4) + (tc << 1);
        float x00 = sp[cb * TTP + tl], x01 = sp[(cb + 1) * TTP + tl];
        float x10 = sp[cb * TTP + tl + 8], x11 = sp[(cb + 1) * TTP + tl + 8];
        float x20 = sp[(cb + 8) * TTP + tl], x21 = sp[(cb + 9) * TTP + tl];
        float x30 = sp[(cb + 8) * TTP + tl + 8], x31 = sp[(cb + 9) * TTP + tl + 8];
        uint32_t ahi[4], alo[4];
        ahi[0] = cvt2(x00, x01); alo[0] = cvt2lo(x00, x01, ahi[0]);
        ahi[1] = cvt2(x10, x11); alo[1] = cvt2lo(x10, x11, ahi[1]);
        ahi[2] = cvt2(x20, x21); alo[2] = cvt2lo(x20, x21, ahi[2]);
        ahi[3] = cvt2(x30, x31); alo[3] = cvt2lo(x30, x31, ahi[3]);
#pragma unroll
        for (int ni2 = 0; ni2 < 4; ni2++) {
            uint32_t ro = smem_u + bpair + (uint32_t)(ni2 * 16 * 144 + s * 32);
            uint32_t e0, e1, o0, o1, f0, f1, p0, p1;
            ldsm4(e0, e1, o0, o1, ro + WGH_B);
            ldsm4(f0, f1, p0, p1, ro + WGL_B);
            mma16816(acc[2 * ni2], ahi, e0, e1);
            mma16816(acc[2 * ni2], alo, e0, e1);
            mma16816(acc[2 * ni2], ahi, f0, f1);
            mma16816(acc[2 * ni2 + 1], ahi, o0, o1);
            mma16816(acc[2 * ni2 + 1], alo, o0, o1);
            mma16816(acc[2 * ni2 + 1], ahi, p0, p1);
        }
    }

    float gate[4][4];
#pragma unroll
    for (int ni = 0; ni < 4; ni++) {
        int n0 = ni * 8 + 2 * tc;
        float bs0 = sBias[n0], bs1 = sBias[n0 + 1];
        float bt0 = sBias[32 + n0], bt1 = sBias[32 + n0 + 1];
#pragma unroll
        for (int h = 0; h < 2; h++) {
            float ds0 = acc[ni][2 * h] + bs0, dt0 = acc[ni + 4][2 * h] + bt0;
            float ds1 = acc[ni][2 * h + 1] + bs1, dt1 = acc[ni + 4][2 * h + 1] + bt1;
            float s0 = __fdividef(1.f, 1.f + __expf(-ds0));
            float s1 = __fdividef(1.f, 1.f + __expf(-ds1));
            float th0 = 1.f - __fdividef(2.f, __expf(2.f * dt0) + 1.f);
            float th1 = 1.f - __fdividef(2.f, __expf(2.f * dt1) + 1.f);
            gate[ni][2 * h] = s0 * th0;
            gate[ni][2 * h + 1] = s1 * th1;
        }
    }

    float racc[4][4];
#pragma unroll
    for (int ot = 0; ot < 4; ot++) {
        int n0 = ot * 8 + 2 * tc;
        racc[ot][0] = sBias[64 + n0];
        racc[ot][1] = sBias[64 + n0 + 1];
        racc[ot][2] = racc[ot][0];
        racc[ot][3] = racc[ot][1];
    }
#pragma unroll
    for (int kk = 0; kk < 2; kk++) {
        uint32_t ah[4], al[4];
        ah[0] = cvt2(gate[2 * kk][0], gate[2 * kk][1]);
        al[0] = cvt2lo(gate[2 * kk][0], gate[2 * kk][1], ah[0]);
        ah[1] = cvt2(gate[2 * kk][2], gate[2 * kk][3]);
        al[1] = cvt2lo(gate[2 * kk][2], gate[2 * kk][3], ah[1]);
        ah[2] = cvt2(gate[2 * kk + 1][0], gate[2 * kk + 1][1]);
        al[2] = cvt2lo(gate[2 * kk + 1][0], gate[2 * kk + 1][1], ah[2]);
        ah[3] = cvt2(gate[2 * kk + 1][2], gate[2 * kk + 1][3]);
        al[3] = cvt2lo(gate[2 * kk + 1][2], gate[2 * kk + 1][3], ah[3]);
#pragma unroll
        for (int ot2 = 0; ot2 < 2; ot2++) {
            uint32_t ro = smem_u + bpair + (uint32_t)(ot2 * 16 * 144 + kk * 32);
            uint32_t e0, e1, o0, o1, f0, f1, p0, p1;
            ldsm4(e0, e1, o0, o1, ro + WRH_B);
            ldsm4(f0, f1, p0, p1, ro + WRL_B);
            mma16816(racc[2 * ot2], ah, e0, e1);
            mma16816(racc[2 * ot2], al, e0, e1);
            mma16816(racc[2 * ot2], ah, f0, f1);
            mma16816(racc[2 * ot2 + 1], ah, o0, o1);
            mma16816(racc[2 * ot2 + 1], al, o0, o1);
            mma16816(racc[2 * ot2 + 1], ah, p0, p1);
        }
    }

#pragma unroll
    for (int ni = 0; ni < 4; ni++) {
        int n0 = ni * 8 + 2 * tc;
#pragma unroll
        for (int h = 0; h < 2; h++) {
            int t = tl + 8 * h;
            sA0[n0 * TTP + t] = gate[ni][2 * h];
            sA0[(n0 + 1) * TTP + t] = gate[ni][2 * h + 1];
        }
    }

    {
        float* outb = outp + (size_t)b * NRES * Lo_s;
#pragma unroll
        for (int ot = 0; ot < 4; ot++) {
            int cbase = ot * 8 + 2 * tc;
#pragma unroll
            for (int h = 0; h < 2; h++) {
                int t = t0 + tl + 8 * h;
                if (t < Lout) {
                    float a0 = sA1[cbase * TTP + tl + 8 * h];
                    float a1 = sA1[(cbase + 1) * TTP + tl + 8 * h];
                    outb[(size_t)cbase * Lo_s + t] = racc[ot][2 * h] + a0;
                    outb[(size_t)(cbase + 1) * Lo_s + t] = racc[ot][2 * h + 1] + a1;
                }
            }
        }
    }
    __syncwarp();

    // gate -> single fp16 plane [b][t][layer*32 + c]
    const int off = Lout - FINALW;
#pragma unroll
    for (int k = 0; k < 8; k++) {
        int idx = lane + 32 * k;
        int ttl = idx >> 4, cp = idx & 15;
        int tt = (w << 4) + ttl;
        int t = t0 + tt;
        if (t < Lout && t >= off) {
            int c2 = 2 * cp;
            float v0 = sA0[c2 * TTP + tt];
            float v1 = sA0[(c2 + 1) * TTP + tt];
            size_t oo = ((size_t)b * FINALW + (t - off)) * 1600 + layer * 32 + c2;
            *reinterpret_cast<__half2*>(g_gateT + oo) = __floats2half2_rn(v0, v1);
        }
    }
}

// ---- unified fp16 GEMM, CTA 128m x 128n, 4 warps ----
// MODE 0: K=1600, SINGLE-term A (fp16 weights, |err|~2.4e-4), bias=sumb, ELU -> h1T
// MODE 1: K=512, 2-term A, bias=param, ELU -> h2T
// MODE 2: K=512, 2-term A, bias=param -> fp32 out
#define LROW2 80
#define A_LO_OFF0 10240
#define B_OFF0 20480
#define STAGE0 30720
#define GSM0_BYTES 67584
template <int MODE>
__global__ __launch_bounds__(128, 2) void k_wmma(const float* __restrict__ bias_in,
                                                 float* __restrict__ Cext) {
    constexpr int K = (MODE == 0) ? 1600 : 512;
    constexpr int NC = K / 32;
    constexpr bool TWO = (MODE != 0);
    const __half* Ahi = (MODE == 0) ? g_A0hi : (MODE == 1) ? g_A1hi : g_A2hi;
    const __half* Alo = (MODE == 0) ? g_A0lo : (MODE == 1) ? g_A1lo : g_A2lo;
    const __half* Bp = (MODE == 0) ? g_gateT : (MODE == 1) ? g_h1T : g_h2T;

    extern __shared__ char smem[];
    const uint32_t smem_u = smem_to_u32(smem);
    const int tid = threadIdx.x, wid = tid >> 5, lane = tid & 31;
    const int m0 = blockIdx.x * 128;
    const int t0 = blockIdx.y * 128;
    const int b = blockIdx.z;
    const int wm = (wid >> 1) * 64, wn = (wid & 1) * 64;

    const __half* Brp = Bp + (size_t)b * FINALW * K;

    float acc[4][8][4];
#pragma unroll
    for (int mi = 0; mi < 4; mi++)
#pragma unroll
        for (int ni = 0; ni < 8; ni++)
#pragma unroll
            for (int e = 0; e < 4; e++) acc[mi][ni][e] = 0.f;

    const uint32_t rA4 = (wm + (lane & 15)) * LROW2 + (lane >> 4) * 16;
    const uint32_t rB4 = B_OFF0 + (wn + ((lane >> 4) & 1) * 8 + (lane & 7)) * LROW2 +
                         ((lane >> 3) & 1) * 16;

    const int lrow = tid >> 2, lunit = tid & 3;

    auto load_chunk = [&](int ch, int buf) {
        const uint32_t st = smem_u + buf * STAGE0;
        const int k0 = ch * 32;
#pragma unroll
        for (int i = 0; i < 4; i++) {
            int r = lrow + 32 * i;
            uint32_t soff = (uint32_t)(r * LROW2 + lunit * 16);
            size_t aoff = (size_t)(m0 + r) * K + k0 + lunit * 8;
            cpa16(st + soff, Ahi + aoff);
            if (TWO) cpa16(st + A_LO_OFF0 + soff, Alo + aoff);
            int t = t0 + r;
            bool pr = t < FINALW;
            int tcl = pr ? t : (FINALW - 1);
            cpa16z(st + B_OFF0 + soff, Brp + (size_t)tcl * K + k0 + lunit * 8, pr);
        }
        CP_COMMIT();
    };

    load_chunk(0, 0);
    for (int ch = 0; ch < NC; ch++) {
        if (ch + 1 < NC) {
            load_chunk(ch + 1, (ch + 1) & 1);
            CP_WAIT(1);
        } else {
            CP_WAIT(0);
        }
        __syncthreads();
        const uint32_t base = smem_u + (ch & 1) * STAGE0;
        const uint32_t aAh = base + rA4, aAl = aAh + A_LO_OFF0;
        const uint32_t aB4 = base + rB4;
#pragma unroll
        for (int k16 = 0; k16 < 2; k16++) {
            uint32_t ah[4][4], al[4][4];
#pragma unroll
            for (int mi = 0; mi < 4; mi++) {
                ldsm4(ah[mi][0], ah[mi][1], ah[mi][2], ah[mi][3],
                      aAh + mi * (16 * LROW2) + k16 * 32);
                if (TWO)
                    ldsm4(al[mi][0], al[mi][1], al[mi][2], al[mi][3],
                          aAl + mi * (16 * LROW2) + k16 * 32);
            }
#pragma unroll
            for (int ni2 = 0; ni2 < 4; ni2++) {
                uint32_t e0, e1, o0, o1;
                ldsm4(e0, e1, o0, o1, aB4 + ni2 * (16 * LROW2) + k16 * 32);
#pragma unroll
                for (int mi = 0; mi < 4; mi++) {
                    mma16816h(acc[mi][2 * ni2], ah[mi], e0, e1);
                    if (TWO) mma16816h(acc[mi][2 * ni2], al[mi], e0, e1);
                    mma16816h(acc[mi][2 * ni2 + 1], ah[mi], o0, o1);
                    if (TWO) mma16816h(acc[mi][2 * ni2 + 1], al[mi], o0, o1);
                }
            }
        }
        __syncthreads();
    }

    // ---- epilogue ----
    const int g = lane >> 2, tig = lane & 3;
    const float* bias = (MODE == 0) ? g_sumb : bias_in;
    float bv[4][2];
#pragma unroll
    for (int mi = 0; mi < 4; mi++)
#pragma unroll
        for (int h = 0; h < 2; h++) bv[mi][h] = bias[m0 + wm + mi * 16 + g + 8 * h];

    if (MODE == 2) {
#pragma unroll
        for (int mi = 0; mi < 4; mi++)
#pragma unroll
            for (int ni = 0; ni < 8; ni++)
#pragma unroll
                for (int h = 0; h < 2; h++)
#pragma unroll
                    for (int p = 0; p < 2; p++) {
                        int t = t0 + wn + ni * 8 + 2 * tig + p;
                        if (t < FINALW) {
                            int m = m0 + wm + mi * 16 + g + 8 * h;
                            Cext[((size_t)b * 256 + m) * FINALW + t] =
                                acc[mi][ni][h * 2 + p] + bv[mi][h];
                        }
                    }
        return;
    }

    __syncthreads();
    float* sT = reinterpret_cast<float*>(smem);  // [128 n][132]
#pragma unroll
    for (int mi = 0; mi < 4; mi++)
#pragma unroll
        for (int ni = 0; ni < 8; ni++)
#pragma unroll
            for (int h = 0; h < 2; h++)
#pragma unroll
                for (int p = 0; p < 2; p++) {
                    float v = elu_f(acc[mi][ni][h * 2 + p] + bv[mi][h]);
                    int n = wn + ni * 8 + 2 * tig + p;
                    int m = wm + mi * 16 + g + 8 * h;
                    sT[n * 132 + m] = v;
                }
    __syncthreads();
    __half* Op = (MODE == 0) ? g_h1T : g_h2T;
    for (int idx = tid; idx < 128 * 64; idx += 128) {
        int t = idx >> 6, mp = idx & 63;
        int tg = t0 + t;
        if (tg < FINALW) {
            float v0 = sT[t * 132 + 2 * mp];
            float v1 = sT[t * 132 + 2 * mp + 1];
            size_t o = ((size_t)b * FINALW + tg) * 512 + m0 + 2 * mp;
            *reinterpret_cast<__half2*>(Op + o) = __floats2half2_rn(v0, v1);
        }
    }
}

// ---------------- launch ----------------
extern "C" void kernel_launch(void* const* d_in, const int* in_sizes, int n_in,
                              void* d_out, int out_size) {
    (void)in_sizes; (void)n_in; (void)out_size;
    const float* x = (const float*)d_in[0];
    const float* w_in = (const float*)d_in[1];
    const float* b_in = (const float*)d_in[2];
    const float* w_sig = (const float*)d_in[3];
    const float* b_sig = (const float*)d_in[4];
    const float* w_tanh = (const float*)d_in[5];
    const float* b_tanh = (const float*)d_in[6];
    const float* w_skip = (const float*)d_in[7];
    const float* b_skip = (const float*)d_in[8];
    const float* w_res = (const float*)d_in[9];
    const float* b_res = (const float*)d_in[10];
    const float* w_post1 = (const float*)d_in[11];
    const float* b_post1 = (const float*)d_in[12];
    const float* w_post2 = (const float*)d_in[13];
    const float* b_post2 = (const float*)d_in[14];
    float* out = (float*)d_out;

    static int inited = 0;
    if (!inited) {
        cudaFuncSetAttribute(k_wmma<0>, cudaFuncAttributeMaxDynamicSharedMemorySize, GSM0_BYTES);
        cudaFuncSetAttribute(k_wmma<1>, cudaFuncAttributeMaxDynamicSharedMemorySize, GSM0_BYTES);
        cudaFuncSetAttribute(k_wmma<2>, cudaFuncAttributeMaxDynamicSharedMemorySize, GSM0_BYTES);
        cudaFuncSetAttribute(k_layer, cudaFuncAttributeMaxDynamicSharedMemorySize, LSM_BYTES);
        inited = 1;
    }

    k_pack<<<5736, 256>>>(w_skip, b_skip, w_post1, w_post2, w_sig, w_tanh, w_res);

    dim3 gin(LFULL / TT, BATCH);
    k_input<<<gin, 256>>>(x, w_in, b_in);

    int Lin = LFULL, Ls = LFULL;
    int flag = 0;
    for (int i = 0; i < NLAYER; i++) {
        int d = 1 << (i % 10);
        int Lout = Lin - d;
        int Lo_s = (Lout + 3) & ~3;
        dim3 g((Lout + TT - 1) / TT, BATCH);
        k_layer<<<g, 256, LSM_BYTES>>>(flag, b_sig + i * 32, b_tanh + i * 32,
                                       b_res + i * 32, d, Lin, Ls, Lo_s, i);
        Lin = Lout;
        Ls = Lo_s;
        flag ^= 1;
    }

    const int NT = (FINALW + 127) / 128;  // 89
    k_wmma<0><<<dim3(4, NT, BATCH), 128, GSM0_BYTES>>>(nullptr, nullptr);
    k_wmma<1><<<dim3(4, NT, BATCH), 128, GSM0_BYTES>>>(b_post1, nullptr);
    k_wmma<2><<<dim3(2, NT, BATCH), 128, GSM0_BYTES>>>(b_post2, out);
}